// round 15
// baseline (speedup 1.0000x reference)
#include <cuda_runtime.h>
#include <cuda_fp16.h>
#include <cstdint>

// Problem constants
#define NUM_AUTHOR 16604
#define NUM_NODES  29059
#define DIM        300
#define NB         32768
#define NE         1048576

// GEMM shape: proj = emb[29059,300] @ Wcat[960,300]^T  (padded M=29184, K=320)
#define MPAD  29184        // 228 * 128
#define KH    320          // padded K (halves)
#define NPADC 960          // 3 sections x 320 cols
#define PSTR  960          // proj row stride (halves)

// Scratch (device globals; allocation-free rule)
__device__ __half g_embh[(size_t)MPAD * KH];     // fp16 emb, fully zero-padded (18.7 MB)
__device__ __half g_wcath[(size_t)NPADC * KH];   // fp16 remapped W1
__device__ __half g_proj[(size_t)MPAD * PSTR];   // projected table, fp16 (56 MB)
__device__ float  g_rsB[DIM];                    // rowsum of Wb (empty-type-1 fallback)
__device__ float  g_rsC[DIM];                    // rowsum of Wc (empty-type-2 fallback)
__device__ int    g_off[NB + 1];

__device__ __forceinline__ void cp_async16(void* sdst, const void* gsrc) {
    uint32_t d = (uint32_t)__cvta_generic_to_shared(sdst);
    asm volatile("cp.async.cg.shared.global [%0], [%1], 16;" :: "r"(d), "l"(gsrc));
}
#define CP_COMMIT() asm volatile("cp.async.commit_group;")
#define CP_WAIT(n)  asm volatile("cp.async.wait_group %0;" :: "n"(n))

// ---------------------------------------------------------------------------
// Kernel 1: fused prep (unchanged from R14)
// ---------------------------------------------------------------------------
#define EMB_BLKS (MPAD / 8)    // 3648
#define OFF_BLKS 205           // ceil((NB+1)/160)
#define PREP_GRID (EMB_BLKS + NPADC + OFF_BLKS)

__global__ void __launch_bounds__(160) prep_kernel(
    const float* __restrict__ emb,
    const float* __restrict__ W1,
    const int*   __restrict__ seg)
{
    __shared__ float s_ws[5];
    int bid = blockIdx.x, t = threadIdx.x;

    if (bid < EMB_BLKS) {
        // ---- embh: 8 rows/block; t -> (row pair, float4 column) ----
        int c4 = t % 80;                     // float4 col 0..79 (75 real + 5 pad)
        int rr = t / 80;                     // 0..1
        bool real = (c4 < 75);
        float4 v[4];
#pragma unroll
        for (int p = 0; p < 4; p++) {        // 4 independent 16B loads
            int row = bid * 8 + p * 2 + rr;
            v[p] = make_float4(0.f, 0.f, 0.f, 0.f);
            if (real && row < NUM_NODES)
                v[p] = *(const float4*)(emb + (size_t)row * DIM + c4 * 4);
        }
#pragma unroll
        for (int p = 0; p < 4; p++) {
            int row = bid * 8 + p * 2 + rr;
            __half2 h0 = __floats2half2_rn(v[p].x, v[p].y);
            __half2 h1 = __floats2half2_rn(v[p].z, v[p].w);
            uint2 pk = make_uint2(*(uint32_t*)&h0, *(uint32_t*)&h1);
            *(uint2*)(g_embh + (size_t)row * KH + c4 * 4) = pk;
        }
    } else if (bid < EMB_BLKS + NPADC) {
        // ---- wcath + rowsum fold ----
        int c = bid - EMB_BLKS;
        int sec = c / 320, j = c - sec * 320;
        int k = 2 * t;
        float v0 = 0.f, v1 = 0.f;
        if (j < DIM && k < DIM) {
            float2 w = *(const float2*)(W1 + (size_t)j * (3 * DIM) + sec * DIM + k);
            v0 = w.x; v1 = w.y;
        }
        *(__half2*)(g_wcath + (size_t)c * KH + k) = __floats2half2_rn(v0, v1);

        if (sec != 0 && j < DIM) {     // rowsum of this exact W1 row (fp32)
            float p = v0 + v1;
            int lane = t & 31, w = t >> 5;
#pragma unroll
            for (int o = 16; o; o >>= 1) p += __shfl_xor_sync(0xffffffffu, p, o);
            if (lane == 0) s_ws[w] = p;
            __syncthreads();
            if (t == 0) {
                float s = s_ws[0] + s_ws[1] + s_ws[2] + s_ws[3] + s_ws[4];
                if (sec == 1) g_rsB[j] = s; else g_rsC[j] = s;
            }
        }
    } else {
        // ---- offsets ----
        int i = (bid - EMB_BLKS - NPADC) * 160 + t;
        if (i <= NB) {
            int lo = 0, hi = NE;
            while (lo < hi) {
                int mid = (lo + hi) >> 1;
                if (seg[mid] < i) lo = mid + 1; else hi = mid;
            }
            g_off[i] = lo;
        }
    }
}

// ---------------------------------------------------------------------------
// Kernel 2: GEMM  proj[MPAD,960](fp16) = embh @ wcath^T   (fp16 in, fp32 acc)
// mma m16n8k16.f16; BM=128, BN=96, BKH=32.
// NEW: 8 warps/block (256 thr), warp tile 32x48 (mt2, nt6) -> ~100 regs/thr
//      -> 2 blocks x 8 warps = 16 warps/SM (was 8).
// 16B-chunk XOR swizzle; 3-stage cp.async pipeline (42 KB smem)
// ---------------------------------------------------------------------------
#define BM 128
#define BN 96
#define BKH 32             // halves per K tile
#define NT (KH / BKH)      // 10
#define A_BUFH (BM * BKH)  // 4096 halves (8 KB)
#define B_BUFH (BN * BKH)  // 3072 halves (6 KB)

__device__ __forceinline__ uint32_t lds_h2(const __half* base, int r, int k) {
    int off = r * BKH + ((((k >> 3) ^ ((r >> 1) & 3))) << 3) + (k & 7);
    return *(const uint32_t*)(base + off);
}

__device__ __forceinline__ void load_tiles(const __half* __restrict__ Ag,
                                           const __half* __restrict__ Bg,
                                           __half* sA, __half* sB,
                                           int kt, int tid) {
    int kb = kt * BKH;
#pragma unroll
    for (int i = 0; i < 2; i++) {              // A: 512 16B chunks, 256 thr
        int lin = tid + i * 256;
        int r = lin >> 2, c = lin & 3;
        int sc = c ^ ((r >> 1) & 3);
        cp_async16(sA + r * BKH + sc * 8, Ag + (size_t)r * KH + kb + c * 8);
    }
    {                                          // B: 384 16B chunks
        int r = tid >> 2, c = tid & 3;
        int sc = c ^ ((r >> 1) & 3);
        cp_async16(sB + r * BKH + sc * 8, Bg + (size_t)r * KH + kb + c * 8);
        if (tid < 128) {
            int lin = tid + 256;
            int r2 = lin >> 2, c2 = lin & 3;
            int sc2 = c2 ^ ((r2 >> 1) & 3);
            cp_async16(sB + r2 * BKH + sc2 * 8, Bg + (size_t)r2 * KH + kb + c2 * 8);
        }
    }
}

__global__ void __launch_bounds__(256) proj_gemm_kernel() {
    __shared__ __half sA[3][A_BUFH];   // 24 KB
    __shared__ __half sB[3][B_BUFH];   // 18 KB

    int bn = blockIdx.x;      // 0..9
    int bm = blockIdx.y;      // 0..227
    int tid = threadIdx.x;
    int warp = tid >> 5, lane = tid & 31;
    int wm = warp & 3, wn = warp >> 2;        // 4 m-warps x 2 n-warps
    int gid = lane >> 2, tig = lane & 3;

    int bmBase = bm * BM;
    const __half* Ag = g_embh + (size_t)bmBase * KH;
    const __half* Bg = g_wcath + (size_t)(bn * BN) * KH;

    float c[2][6][4];
#pragma unroll
    for (int mt = 0; mt < 2; mt++)
#pragma unroll
        for (int nt = 0; nt < 6; nt++)
#pragma unroll
            for (int i = 0; i < 4; i++) c[mt][nt][i] = 0.f;

    load_tiles(Ag, Bg, sA[0], sB[0], 0, tid);
    CP_COMMIT();
    load_tiles(Ag, Bg, sA[1], sB[1], 1, tid);
    CP_COMMIT();

    int buf = 0, nbuf = 2;
    for (int kt = 0; kt < NT; kt++) {
        if (kt + 1 < NT) { CP_WAIT(1); } else { CP_WAIT(0); }
        __syncthreads();
        if (kt + 2 < NT) {
            load_tiles(Ag, Bg, sA[nbuf], sB[nbuf], kt + 2, tid);
            CP_COMMIT();
        }

        const __half* Ab = sA[buf];
        const __half* Bb = sB[buf];

#pragma unroll
        for (int ks = 0; ks < 2; ks++) {
            int k0 = ks * 16;
            uint32_t a[2][4], bfr[6][2];
#pragma unroll
            for (int mt = 0; mt < 2; mt++) {
                int r0 = wm * 32 + mt * 16 + gid;
                a[mt][0] = lds_h2(Ab, r0,     k0 + 2 * tig);
                a[mt][1] = lds_h2(Ab, r0 + 8, k0 + 2 * tig);
                a[mt][2] = lds_h2(Ab, r0,     k0 + 8 + 2 * tig);
                a[mt][3] = lds_h2(Ab, r0 + 8, k0 + 8 + 2 * tig);
            }
#pragma unroll
            for (int nt = 0; nt < 6; nt++) {
                int n = wn * 48 + nt * 8 + gid;
                bfr[nt][0] = lds_h2(Bb, n, k0 + 2 * tig);
                bfr[nt][1] = lds_h2(Bb, n, k0 + 8 + 2 * tig);
            }
#pragma unroll
            for (int mt = 0; mt < 2; mt++)
#pragma unroll
                for (int nt = 0; nt < 6; nt++) {
                    asm volatile(
                        "mma.sync.aligned.m16n8k16.row.col.f32.f16.f16.f32 "
                        "{%0,%1,%2,%3},{%4,%5,%6,%7},{%8,%9},{%0,%1,%2,%3};"
                        : "+f"(c[mt][nt][0]), "+f"(c[mt][nt][1]),
                          "+f"(c[mt][nt][2]), "+f"(c[mt][nt][3])
                        : "r"(a[mt][0]), "r"(a[mt][1]), "r"(a[mt][2]), "r"(a[mt][3]),
                          "r"(bfr[nt][0]), "r"(bfr[nt][1]));
                }
        }
        buf = (buf == 2) ? 0 : buf + 1;
        nbuf = (nbuf == 2) ? 0 : nbuf + 1;
    }

    // Epilogue: fp16 store (bias added later in agg)
#pragma unroll
    for (int mt = 0; mt < 2; mt++) {
#pragma unroll
        for (int nt = 0; nt < 6; nt++) {
            int gm = bmBase + wm * 32 + mt * 16 + gid;
            int gn = bn * BN + wn * 48 + nt * 8 + tig * 2;
            __half2 h0 = __floats2half2_rn(c[mt][nt][0], c[mt][nt][1]);
            __half2 h1 = __floats2half2_rn(c[mt][nt][2], c[mt][nt][3]);
            *(__half2*)(g_proj + (size_t)gm * PSTR + gn) = h0;
            *(__half2*)(g_proj + (size_t)(gm + 8) * PSTR + gn) = h1;
        }
    }
}

// ---------------------------------------------------------------------------
// Kernel 3: aggregation. Block = one node (32k blocks). 75 threads,
// thread = 4 dims (uint2). Edges block-uniform. int4 index loads (via L1 —
// reused across the block's warps). NEW: proj gathers via __ldcg (.cg =
// bypass L1, cache in L2 where the reuse lives). __stcs output store.
// ---------------------------------------------------------------------------
#define CHUNK 16
#define AGG_T 75

__global__ void __launch_bounds__(AGG_T) agg_kernel(
    const int* __restrict__ nodes,
    const int* __restrict__ neighbors,
    const float* __restrict__ b1,
    float* __restrict__ out)
{
    int b = blockIdx.x;
    int tid = threadIdx.x;
    int start = g_off[b];
    int end   = g_off[b + 1];
    int node  = nodes[b];
    bool selfA = node < NUM_AUTHOR;
    const __half2 z2 = __float2half2_rn(0.f);

    float2 a1l = {0.f, 0.f}, a1h = {0.f, 0.f};
    float2 a2l = {0.f, 0.f}, a2h = {0.f, 0.f};
    int c1 = 0;

    int e = start;

    // peel to 4-edge (16B) alignment of the index array
    {
        int pre = (4 - (e & 3)) & 3;
        if (pre > end - e) pre = end - e;
        __half2 p1l = z2, p1h = z2, p2l = z2, p2h = z2;
        for (int q = 0; q < pre; q++, e++) {
            int n = neighbors[e];
            bool s = (n < NUM_AUTHOR) == selfA;
            uint2 v = __ldcg((const uint2*)(g_proj + (size_t)n * PSTR + (s ? 320 : 640)) + tid);
            const __half2* hv = (const __half2*)&v;
            if (s) { p1l = __hadd2(p1l, hv[0]); p1h = __hadd2(p1h, hv[1]); c1++; }
            else   { p2l = __hadd2(p2l, hv[0]); p2h = __hadd2(p2h, hv[1]); }
        }
        float2 f;
        f = __half22float2(p1l); a1l.x += f.x; a1l.y += f.y;
        f = __half22float2(p1h); a1h.x += f.x; a1h.y += f.y;
        f = __half22float2(p2l); a2l.x += f.x; a2l.y += f.y;
        f = __half22float2(p2h); a2h.x += f.x; a2h.y += f.y;
    }

    // main: 16-edge chunks, indices via 4x LDG.128
    for (; e + CHUNK <= end; e += CHUNK) {
        int4 q0 = *(const int4*)(neighbors + e);
        int4 q1 = *(const int4*)(neighbors + e + 4);
        int4 q2 = *(const int4*)(neighbors + e + 8);
        int4 q3 = *(const int4*)(neighbors + e + 12);
        int nn[CHUNK] = {q0.x, q0.y, q0.z, q0.w, q1.x, q1.y, q1.z, q1.w,
                         q2.x, q2.y, q2.z, q2.w, q3.x, q3.y, q3.z, q3.w};
        bool ss[CHUNK];
        uint2 h[CHUNK];
#pragma unroll
        for (int j = 0; j < CHUNK; j++) {
            ss[j] = (nn[j] < NUM_AUTHOR) == selfA;
            h[j] = __ldcg((const uint2*)(g_proj + (size_t)nn[j] * PSTR + (ss[j] ? 320 : 640)) + tid);
        }
        __half2 p1l = z2, p1h = z2, p2l = z2, p2h = z2;
#pragma unroll
        for (int j = 0; j < CHUNK; j++) {
            const __half2* hv = (const __half2*)&h[j];
            if (ss[j]) { p1l = __hadd2(p1l, hv[0]); p1h = __hadd2(p1h, hv[1]); c1++; }
            else       { p2l = __hadd2(p2l, hv[0]); p2h = __hadd2(p2h, hv[1]); }
        }
        float2 f;
        f = __half22float2(p1l); a1l.x += f.x; a1l.y += f.y;
        f = __half22float2(p1h); a1h.x += f.x; a1h.y += f.y;
        f = __half22float2(p2l); a2l.x += f.x; a2l.y += f.y;
        f = __half22float2(p2h); a2h.x += f.x; a2h.y += f.y;
    }

    // remainder (< CHUNK edges)
    {
        __half2 p1l = z2, p1h = z2, p2l = z2, p2h = z2;
        for (; e < end; e++) {
            int n = neighbors[e];
            bool s = (n < NUM_AUTHOR) == selfA;
            uint2 v = __ldcg((const uint2*)(g_proj + (size_t)n * PSTR + (s ? 320 : 640)) + tid);
            const __half2* hv = (const __half2*)&v;
            if (s) { p1l = __hadd2(p1l, hv[0]); p1h = __hadd2(p1h, hv[1]); c1++; }
            else   { p2l = __hadd2(p2l, hv[0]); p2h = __hadd2(p2h, hv[1]); }
        }
        float2 f;
        f = __half22float2(p1l); a1l.x += f.x; a1l.y += f.y;
        f = __half22float2(p1h); a1h.x += f.x; a1h.y += f.y;
        f = __half22float2(p2l); a2l.x += f.x; a2l.y += f.y;
        f = __half22float2(p2h); a2h.x += f.x; a2h.y += f.y;
    }

    {                                     // all 75 threads: dims [tid*4, tid*4+4)
        int tot = end - start;
        int c2 = tot - c1;
        int d = tid * 4;
        float t1[4], t2[4];
        if (c1 > 0) {
            float r = 1.0f / (float)c1;
            t1[0] = a1l.x * r; t1[1] = a1l.y * r; t1[2] = a1h.x * r; t1[3] = a1h.y * r;
        } else {
            t1[0] = g_rsB[d]; t1[1] = g_rsB[d + 1]; t1[2] = g_rsB[d + 2]; t1[3] = g_rsB[d + 3];
        }
        if (c2 > 0) {
            float r = 1.0f / (float)c2;
            t2[0] = a2l.x * r; t2[1] = a2l.y * r; t2[2] = a2h.x * r; t2[3] = a2h.y * r;
        } else {
            t2[0] = g_rsC[d]; t2[1] = g_rsC[d + 1]; t2[2] = g_rsC[d + 2]; t2[3] = g_rsC[d + 3];
        }

        uint2 sv = __ldcg((const uint2*)(g_proj + (size_t)node * PSTR) + tid);
        const __half2* sp = (const __half2*)&sv;
        float2 s0 = __half22float2(sp[0]);
        float2 s1 = __half22float2(sp[1]);
        float4 bb = *(const float4*)(b1 + d);

        float4 o;
        o.x = s0.x + t1[0] + t2[0] + bb.x;
        o.y = s0.y + t1[1] + t2[1] + bb.y;
        o.z = s1.x + t1[2] + t2[2] + bb.z;
        o.w = s1.y + t1[3] + t2[3] + bb.w;
        __stcs((float4*)(out + (size_t)b * DIM + d), o);   // (b*300+d) % 4 == 0
    }
}

// ---------------------------------------------------------------------------
extern "C" void kernel_launch(void* const* d_in, const int* in_sizes, int n_in,
                              void* d_out, int out_size) {
    const int*   nodes     = (const int*)d_in[0];
    const int*   seg       = (const int*)d_in[1];
    const int*   neighbors = (const int*)d_in[2];
    const float* emb       = (const float*)d_in[3];
    const float* W1        = (const float*)d_in[4];
    const float* b1        = (const float*)d_in[5];
    float*       out       = (float*)d_out;

    prep_kernel<<<PREP_GRID, 160>>>(emb, W1, seg);
    dim3 ggrid(NPADC / BN, MPAD / BM);   // (10, 228), x-fast shares A via L2
    proj_gemm_kernel<<<ggrid, 256>>>();
    agg_kernel<<<NB, AGG_T>>>(nodes, neighbors, b1, out);
}

// round 16
// speedup vs baseline: 1.0741x; 1.0741x over previous
#include <cuda_runtime.h>
#include <cuda_fp16.h>
#include <cstdint>

// Problem constants
#define NUM_AUTHOR 16604
#define NUM_NODES  29059
#define DIM        300
#define NB         32768
#define NE         1048576

// GEMM shape: proj = emb[29059,300] @ Wcat[960,300]^T  (padded M=29184, K=320)
#define MPAD  29184        // 228 * 128
#define KH    320          // padded K (halves)
#define NPADC 960          // 3 sections x 320 cols
#define PSTR  960          // proj row stride (halves)

// Scratch (device globals; allocation-free rule)
__device__ __half g_embh[(size_t)MPAD * KH];     // fp16 emb, fully zero-padded (18.7 MB)
__device__ __half g_wcath[(size_t)NPADC * KH];   // fp16 remapped W1
__device__ __half g_proj[(size_t)MPAD * PSTR];   // projected table, fp16 (56 MB)
__device__ float  g_rsB[DIM];                    // rowsum of Wb (empty-type-1 fallback)
__device__ float  g_rsC[DIM];                    // rowsum of Wc (empty-type-2 fallback)
__device__ int    g_off[NB + 1];

__device__ __forceinline__ void cp_async16(void* sdst, const void* gsrc) {
    uint32_t d = (uint32_t)__cvta_generic_to_shared(sdst);
    asm volatile("cp.async.cg.shared.global [%0], [%1], 16;" :: "r"(d), "l"(gsrc));
}
#define CP_COMMIT() asm volatile("cp.async.commit_group;")
#define CP_WAIT(n)  asm volatile("cp.async.wait_group %0;" :: "n"(n))

#define LDSM_X4(r0, r1, r2, r3, addr)                                        \
    asm volatile("ldmatrix.sync.aligned.m8n8.x4.shared.b16 {%0,%1,%2,%3}, [%4];" \
                 : "=r"(r0), "=r"(r1), "=r"(r2), "=r"(r3) : "r"(addr))

// ---------------------------------------------------------------------------
// Kernel 1: fused prep (unchanged from R14)
// ---------------------------------------------------------------------------
#define EMB_BLKS (MPAD / 8)    // 3648
#define OFF_BLKS 205           // ceil((NB+1)/160)
#define PREP_GRID (EMB_BLKS + NPADC + OFF_BLKS)

__global__ void __launch_bounds__(160) prep_kernel(
    const float* __restrict__ emb,
    const float* __restrict__ W1,
    const int*   __restrict__ seg)
{
    __shared__ float s_ws[5];
    int bid = blockIdx.x, t = threadIdx.x;

    if (bid < EMB_BLKS) {
        int c4 = t % 80;                     // float4 col 0..79 (75 real + 5 pad)
        int rr = t / 80;                     // 0..1
        bool real = (c4 < 75);
        float4 v[4];
#pragma unroll
        for (int p = 0; p < 4; p++) {
            int row = bid * 8 + p * 2 + rr;
            v[p] = make_float4(0.f, 0.f, 0.f, 0.f);
            if (real && row < NUM_NODES)
                v[p] = *(const float4*)(emb + (size_t)row * DIM + c4 * 4);
        }
#pragma unroll
        for (int p = 0; p < 4; p++) {
            int row = bid * 8 + p * 2 + rr;
            __half2 h0 = __floats2half2_rn(v[p].x, v[p].y);
            __half2 h1 = __floats2half2_rn(v[p].z, v[p].w);
            uint2 pk = make_uint2(*(uint32_t*)&h0, *(uint32_t*)&h1);
            *(uint2*)(g_embh + (size_t)row * KH + c4 * 4) = pk;
        }
    } else if (bid < EMB_BLKS + NPADC) {
        int c = bid - EMB_BLKS;
        int sec = c / 320, j = c - sec * 320;
        int k = 2 * t;
        float v0 = 0.f, v1 = 0.f;
        if (j < DIM && k < DIM) {
            float2 w = *(const float2*)(W1 + (size_t)j * (3 * DIM) + sec * DIM + k);
            v0 = w.x; v1 = w.y;
        }
        *(__half2*)(g_wcath + (size_t)c * KH + k) = __floats2half2_rn(v0, v1);

        if (sec != 0 && j < DIM) {
            float p = v0 + v1;
            int lane = t & 31, w = t >> 5;
#pragma unroll
            for (int o = 16; o; o >>= 1) p += __shfl_xor_sync(0xffffffffu, p, o);
            if (lane == 0) s_ws[w] = p;
            __syncthreads();
            if (t == 0) {
                float s = s_ws[0] + s_ws[1] + s_ws[2] + s_ws[3] + s_ws[4];
                if (sec == 1) g_rsB[j] = s; else g_rsC[j] = s;
            }
        }
    } else {
        int i = (bid - EMB_BLKS - NPADC) * 160 + t;
        if (i <= NB) {
            int lo = 0, hi = NE;
            while (lo < hi) {
                int mid = (lo + hi) >> 1;
                if (seg[mid] < i) lo = mid + 1; else hi = mid;
            }
            g_off[i] = lo;
        }
    }
}

// ---------------------------------------------------------------------------
// Kernel 2: GEMM  proj[MPAD,960](fp16) = embh @ wcath^T   (fp16 in, fp32 acc)
// mma m16n8k16.f16; BM=128, BN=96, BKH=32; 4 warps (2m x 2n), wtile 64x48
// 16B-chunk XOR swizzle; 3-stage cp.async pipeline (42 KB smem)
// NEW (only change vs R14): fragment loads via ldmatrix.x4 (LDSM) —
// 14 LDSM per kt instead of 56 LDS.32. Same layout, same math.
// ---------------------------------------------------------------------------
#define BM 128
#define BN 96
#define BKH 32             // halves per K tile
#define NT (KH / BKH)      // 10
#define A_BUFH (BM * BKH)  // 4096 halves (8 KB)
#define B_BUFH (BN * BKH)  // 3072 halves (6 KB)

__device__ __forceinline__ void load_tiles(const __half* __restrict__ Ag,
                                           const __half* __restrict__ Bg,
                                           __half* sA, __half* sB,
                                           int kt, int tid) {
    int kb = kt * BKH;
#pragma unroll
    for (int i = 0; i < 4; i++) {              // A: 512 16B chunks
        int lin = tid + i * 128;
        int r = lin >> 2, c = lin & 3;
        int sc = c ^ ((r >> 1) & 3);
        cp_async16(sA + r * BKH + sc * 8, Ag + (size_t)r * KH + kb + c * 8);
    }
#pragma unroll
    for (int i = 0; i < 3; i++) {              // B: 384 16B chunks
        int lin = tid + i * 128;
        int r = lin >> 2, c = lin & 3;
        int sc = c ^ ((r >> 1) & 3);
        cp_async16(sB + r * BKH + sc * 8, Bg + (size_t)r * KH + kb + c * 8);
    }
}

__global__ void __launch_bounds__(128) proj_gemm_kernel() {
    __shared__ __half sA[3][A_BUFH];   // 24 KB
    __shared__ __half sB[3][B_BUFH];   // 18 KB

    int bn = blockIdx.x;      // 0..9
    int bm = blockIdx.y;      // 0..227
    int tid = threadIdx.x;
    int warp = tid >> 5, lane = tid & 31;
    int wm = warp & 1, wn = warp >> 1;
    int gid = lane >> 2, tig = lane & 3;

    int bmBase = bm * BM;
    const __half* Ag = g_embh + (size_t)bmBase * KH;
    const __half* Bg = g_wcath + (size_t)(bn * BN) * KH;

    // ldmatrix per-lane address components (halves; byte = 2x)
    // A x4 (per mt, ks): rows r0..r0+15 at chunk 2ks (lanes 0-15), chunk 2ks+1 (16-31)
    int lHi  = lane >> 4;                 // 0/1 -> k-chunk select for A
    int lMid = (lane >> 3) & 1;           // 0/1 -> k-chunk select for B
    int rowA = wm * 64 + (lane & 15);     // + mt*16
    int swzA = (rowA >> 1) & 3;           // invariant under +mt*16
    // B x4 (per nt-pair p, ks): rows n0..n0+7 (lanes 0-15), n0+8..15 (16-31)
    int nB   = wn * 48 + (lane & 7) + (lHi << 3);   // + p*16
    int swzB = (nB >> 1) & 3;             // invariant under +p*16

    uint32_t sA_u = (uint32_t)__cvta_generic_to_shared(&sA[0][0]);
    uint32_t sB_u = (uint32_t)__cvta_generic_to_shared(&sB[0][0]);

    float c[4][6][4];
#pragma unroll
    for (int mt = 0; mt < 4; mt++)
#pragma unroll
        for (int nt = 0; nt < 6; nt++)
#pragma unroll
            for (int i = 0; i < 4; i++) c[mt][nt][i] = 0.f;

    load_tiles(Ag, Bg, sA[0], sB[0], 0, tid);
    CP_COMMIT();
    load_tiles(Ag, Bg, sA[1], sB[1], 1, tid);
    CP_COMMIT();

    int buf = 0, nbuf = 2;
    for (int kt = 0; kt < NT; kt++) {
        if (kt + 1 < NT) { CP_WAIT(1); } else { CP_WAIT(0); }
        __syncthreads();
        if (kt + 2 < NT) {
            load_tiles(Ag, Bg, sA[nbuf], sB[nbuf], kt + 2, tid);
            CP_COMMIT();
        }

        uint32_t aBase = sA_u + (uint32_t)buf * (A_BUFH * 2);
        uint32_t bBase = sB_u + (uint32_t)buf * (B_BUFH * 2);

#pragma unroll
        for (int ks = 0; ks < 2; ks++) {
            uint32_t a[4][4], bfr[6][2];
            int chA = (2 * ks + lHi)  ^ swzA;   // A k-chunk (swizzled)
            int chB = (2 * ks + lMid) ^ swzB;   // B k-chunk (swizzled)
#pragma unroll
            for (int mt = 0; mt < 4; mt++) {
                uint32_t addr = aBase + 2 * ((rowA + mt * 16) * BKH + (chA << 3));
                LDSM_X4(a[mt][0], a[mt][1], a[mt][2], a[mt][3], addr);
            }
#pragma unroll
            for (int p = 0; p < 3; p++) {
                uint32_t addr = bBase + 2 * ((nB + p * 16) * BKH + (chB << 3));
                LDSM_X4(bfr[2 * p][0], bfr[2 * p][1],
                        bfr[2 * p + 1][0], bfr[2 * p + 1][1], addr);
            }
#pragma unroll
            for (int mt = 0; mt < 4; mt++)
#pragma unroll
                for (int nt = 0; nt < 6; nt++) {
                    asm volatile(
                        "mma.sync.aligned.m16n8k16.row.col.f32.f16.f16.f32 "
                        "{%0,%1,%2,%3},{%4,%5,%6,%7},{%8,%9},{%0,%1,%2,%3};"
                        : "+f"(c[mt][nt][0]), "+f"(c[mt][nt][1]),
                          "+f"(c[mt][nt][2]), "+f"(c[mt][nt][3])
                        : "r"(a[mt][0]), "r"(a[mt][1]), "r"(a[mt][2]), "r"(a[mt][3]),
                          "r"(bfr[nt][0]), "r"(bfr[nt][1]));
                }
        }
        buf = (buf == 2) ? 0 : buf + 1;
        nbuf = (nbuf == 2) ? 0 : nbuf + 1;
    }

    // Epilogue: fp16 store (bias added later in agg)
#pragma unroll
    for (int mt = 0; mt < 4; mt++) {
#pragma unroll
        for (int nt = 0; nt < 6; nt++) {
            int gm = bmBase + wm * 64 + mt * 16 + gid;
            int gn = bn * BN + wn * 48 + nt * 8 + tig * 2;
            __half2 h0 = __floats2half2_rn(c[mt][nt][0], c[mt][nt][1]);
            __half2 h1 = __floats2half2_rn(c[mt][nt][2], c[mt][nt][3]);
            *(__half2*)(g_proj + (size_t)gm * PSTR + gn) = h0;
            *(__half2*)(g_proj + (size_t)(gm + 8) * PSTR + gn) = h1;
        }
    }
}

// ---------------------------------------------------------------------------
// Kernel 3: aggregation (R14 version, verbatim: plain gathers + __stcs out)
// ---------------------------------------------------------------------------
#define CHUNK 16
#define AGG_T 75

__global__ void __launch_bounds__(AGG_T) agg_kernel(
    const int* __restrict__ nodes,
    const int* __restrict__ neighbors,
    const float* __restrict__ b1,
    float* __restrict__ out)
{
    int b = blockIdx.x;
    int tid = threadIdx.x;
    int start = g_off[b];
    int end   = g_off[b + 1];
    int node  = nodes[b];
    bool selfA = node < NUM_AUTHOR;
    const __half2 z2 = __float2half2_rn(0.f);

    float2 a1l = {0.f, 0.f}, a1h = {0.f, 0.f};
    float2 a2l = {0.f, 0.f}, a2h = {0.f, 0.f};
    int c1 = 0;

    int e = start;

    // peel to 4-edge (16B) alignment of the index array
    {
        int pre = (4 - (e & 3)) & 3;
        if (pre > end - e) pre = end - e;
        __half2 p1l = z2, p1h = z2, p2l = z2, p2h = z2;
        for (int q = 0; q < pre; q++, e++) {
            int n = neighbors[e];
            bool s = (n < NUM_AUTHOR) == selfA;
            uint2 v = *((const uint2*)(g_proj + (size_t)n * PSTR + (s ? 320 : 640)) + tid);
            const __half2* hv = (const __half2*)&v;
            if (s) { p1l = __hadd2(p1l, hv[0]); p1h = __hadd2(p1h, hv[1]); c1++; }
            else   { p2l = __hadd2(p2l, hv[0]); p2h = __hadd2(p2h, hv[1]); }
        }
        float2 f;
        f = __half22float2(p1l); a1l.x += f.x; a1l.y += f.y;
        f = __half22float2(p1h); a1h.x += f.x; a1h.y += f.y;
        f = __half22float2(p2l); a2l.x += f.x; a2l.y += f.y;
        f = __half22float2(p2h); a2h.x += f.x; a2h.y += f.y;
    }

    // main: 16-edge chunks, indices via 4x LDG.128
    for (; e + CHUNK <= end; e += CHUNK) {
        int4 q0 = *(const int4*)(neighbors + e);
        int4 q1 = *(const int4*)(neighbors + e + 4);
        int4 q2 = *(const int4*)(neighbors + e + 8);
        int4 q3 = *(const int4*)(neighbors + e + 12);
        int nn[CHUNK] = {q0.x, q0.y, q0.z, q0.w, q1.x, q1.y, q1.z, q1.w,
                         q2.x, q2.y, q2.z, q2.w, q3.x, q3.y, q3.z, q3.w};
        bool ss[CHUNK];
        uint2 h[CHUNK];
#pragma unroll
        for (int j = 0; j < CHUNK; j++) {
            ss[j] = (nn[j] < NUM_AUTHOR) == selfA;
            h[j] = *((const uint2*)(g_proj + (size_t)nn[j] * PSTR + (ss[j] ? 320 : 640)) + tid);
        }
        __half2 p1l = z2, p1h = z2, p2l = z2, p2h = z2;
#pragma unroll
        for (int j = 0; j < CHUNK; j++) {
            const __half2* hv = (const __half2*)&h[j];
            if (ss[j]) { p1l = __hadd2(p1l, hv[0]); p1h = __hadd2(p1h, hv[1]); c1++; }
            else       { p2l = __hadd2(p2l, hv[0]); p2h = __hadd2(p2h, hv[1]); }
        }
        float2 f;
        f = __half22float2(p1l); a1l.x += f.x; a1l.y += f.y;
        f = __half22float2(p1h); a1h.x += f.x; a1h.y += f.y;
        f = __half22float2(p2l); a2l.x += f.x; a2l.y += f.y;
        f = __half22float2(p2h); a2h.x += f.x; a2h.y += f.y;
    }

    // remainder (< CHUNK edges)
    {
        __half2 p1l = z2, p1h = z2, p2l = z2, p2h = z2;
        for (; e < end; e++) {
            int n = neighbors[e];
            bool s = (n < NUM_AUTHOR) == selfA;
            uint2 v = *((const uint2*)(g_proj + (size_t)n * PSTR + (s ? 320 : 640)) + tid);
            const __half2* hv = (const __half2*)&v;
            if (s) { p1l = __hadd2(p1l, hv[0]); p1h = __hadd2(p1h, hv[1]); c1++; }
            else   { p2l = __hadd2(p2l, hv[0]); p2h = __hadd2(p2h, hv[1]); }
        }
        float2 f;
        f = __half22float2(p1l); a1l.x += f.x; a1l.y += f.y;
        f = __half22float2(p1h); a1h.x += f.x; a1h.y += f.y;
        f = __half22float2(p2l); a2l.x += f.x; a2l.y += f.y;
        f = __half22float2(p2h); a2h.x += f.x; a2h.y += f.y;
    }

    {                                     // all 75 threads: dims [tid*4, tid*4+4)
        int tot = end - start;
        int c2 = tot - c1;
        int d = tid * 4;
        float t1[4], t2[4];
        if (c1 > 0) {
            float r = 1.0f / (float)c1;
            t1[0] = a1l.x * r; t1[1] = a1l.y * r; t1[2] = a1h.x * r; t1[3] = a1h.y * r;
        } else {
            t1[0] = g_rsB[d]; t1[1] = g_rsB[d + 1]; t1[2] = g_rsB[d + 2]; t1[3] = g_rsB[d + 3];
        }
        if (c2 > 0) {
            float r = 1.0f / (float)c2;
            t2[0] = a2l.x * r; t2[1] = a2l.y * r; t2[2] = a2h.x * r; t2[3] = a2h.y * r;
        } else {
            t2[0] = g_rsC[d]; t2[1] = g_rsC[d + 1]; t2[2] = g_rsC[d + 2]; t2[3] = g_rsC[d + 3];
        }

        uint2 sv = *((const uint2*)(g_proj + (size_t)node * PSTR) + tid);
        const __half2* sp = (const __half2*)&sv;
        float2 s0 = __half22float2(sp[0]);
        float2 s1 = __half22float2(sp[1]);
        float4 bb = *(const float4*)(b1 + d);

        float4 o;
        o.x = s0.x + t1[0] + t2[0] + bb.x;
        o.y = s0.y + t1[1] + t2[1] + bb.y;
        o.z = s1.x + t1[2] + t2[2] + bb.z;
        o.w = s1.y + t1[3] + t2[3] + bb.w;
        __stcs((float4*)(out + (size_t)b * DIM + d), o);   // (b*300+d) % 4 == 0
    }
}

// ---------------------------------------------------------------------------
extern "C" void kernel_launch(void* const* d_in, const int* in_sizes, int n_in,
                              void* d_out, int out_size) {
    const int*   nodes     = (const int*)d_in[0];
    const int*   seg       = (const int*)d_in[1];
    const int*   neighbors = (const int*)d_in[2];
    const float* emb       = (const float*)d_in[3];
    const float* W1        = (const float*)d_in[4];
    const float* b1        = (const float*)d_in[5];
    float*       out       = (float*)d_out;

    prep_kernel<<<PREP_GRID, 160>>>(emb, W1, seg);
    dim3 ggrid(NPADC / BN, MPAD / BM);   // (10, 228), x-fast shares A via L2
    proj_gemm_kernel<<<ggrid, 128>>>();
    agg_kernel<<<NB, AGG_T>>>(nodes, neighbors, b1, out);
}